// round 17
// baseline (speedup 1.0000x reference)
#include <cuda_runtime.h>
#include <cuda_fp16.h>
#include <math.h>
#include <stdint.h>

// ---------------------------------------------------------------------------
// Problem constants
// ---------------------------------------------------------------------------
#define Bc   4
#define Hc   8
#define SQc  2048
#define SKc  512
#define DMc  4096
#define DKc  512

// ---------------------------------------------------------------------------
// Scratch (device globals). All GEMM operands live in fp16.
// ---------------------------------------------------------------------------
__device__ __half g_qh[(size_t)Bc * SQc * DMc];
__device__ __half g_kh[(size_t)Bc * SKc * DMc];
__device__ __half g_vh[(size_t)Bc * SKc * DMc];
__device__ __half g_ih[(size_t)Bc * SKc * DMc];
__device__ __half g_w0h[(size_t)DMc * DMc];
__device__ __half g_w1h[(size_t)DMc * DMc];
__device__ __half g_w2h[(size_t)DMc * DMc];
__device__ __half g_w3h[(size_t)DMc * DMc];
__device__ __half g_q   [(size_t)Bc * Hc * SQc * DKc];
__device__ __half g_kp  [(size_t)Bc * Hc * SKc * DKc];
__device__ __half g_vt  [(size_t)Bc * Hc * DKc * SKc];
__device__ __half g_imft[(size_t)Bc * Hc * DKc * SKc];
__device__ __half g_sc  [(size_t)Bc * Hc * SQc * SKc];
__device__ __half g_t   [(size_t)Bc * Hc * SQc * DKc];
__device__ __half g_x   [(size_t)Bc * SQc * DMc];

// ---------------------------------------------------------------------------
// Helpers
// ---------------------------------------------------------------------------
__device__ __forceinline__ uint32_t smem_u32(const void* p) {
    uint32_t a;
    asm("{ .reg .u64 t; cvta.to.shared.u64 t, %1; cvt.u32.u64 %0, t; }" : "=r"(a) : "l"(p));
    return a;
}
__device__ __forceinline__ void cp16(uint32_t dst, const __half* src) {
    asm volatile("cp.async.cg.shared.global [%0], [%1], 16;" :: "r"(dst), "l"(src) : "memory");
}
#define CP_COMMIT() asm volatile("cp.async.commit_group;" ::: "memory")
#define CP_WAIT2()  asm volatile("cp.async.wait_group 2;" ::: "memory")
#define LDSM4(r0, r1, r2, r3, addr)                                            \
    asm volatile("ldmatrix.sync.aligned.m8n8.x4.shared.b16 {%0,%1,%2,%3}, [%4];" \
        : "=r"(r0), "=r"(r1), "=r"(r2), "=r"(r3) : "r"(addr))

// ---------------------------------------------------------------------------
// fp16 mma.sync GEMM (NT: C[m,n] = sum_k A[m,k]*B[n,k]), fp32 accum.
// CTA tile 128x256x32, 8 warps (2x4), warp tile 64x64, m16n8k16, ldmatrix.x4.
// 4-stage cp.async pipeline; smem rows padded to 40 halves (conflict-free).
// MODE 0: plain fp32 + bias         MODE 1: split-head + bias -> fp16
// MODE 2: split-head^T + bias->fp16 MODE 3: batched * scale -> fp16
// MODE 4: batched merge-head -> fp16
// ---------------------------------------------------------------------------
#define BM 128
#define BN 256
#define LROWH 40
#define A_TILE_B (BM * LROWH * 2)          // 10240
#define B_TILE_B (BN * LROWH * 2)          // 20480
#define STAGE_B  (A_TILE_B + B_TILE_B)     // 30720
#define GEMM_SMEM (4 * STAGE_B)            // 122880

template <int MODE, int S>
__global__ void __launch_bounds__(256, 1)
tgemm(const __half* __restrict__ A, const __half* __restrict__ Bm,
      const float* __restrict__ bias, void* __restrict__ Cv,
      int M, int N, int K, long long sA, long long sB, long long sC, float scale)
{
    extern __shared__ char smc[];
    const uint32_t sbase = smem_u32(smc);
    const int tid = threadIdx.x;
    const int m0 = blockIdx.y * BM;
    const int n0 = blockIdx.x * BN;
    const int z  = blockIdx.z;

    const __half* Ab = A  + (long long)z * sA;
    const __half* Bb = Bm + (long long)z * sB;

    // loader geometry: A row tid>>1 (2 chunks), B row tid (4 chunks)
    const int arow = tid >> 1;
    const int achk = (tid & 1) * 2;
    const int brow = tid;

    // compute geometry
    const int lane = tid & 31, wid = tid >> 5;
    const int g = lane >> 2, tg = lane & 3;
    const int wm = wid >> 2, wn = wid & 3;          // 2x4 warp grid, 64x64 tiles
    const int mat  = lane >> 3;
    const int mrow = ((mat & 1) << 3) + (lane & 7);
    const int kcol = (mat >> 1) << 3;

    uint32_t offA[4], offB[4];
#pragma unroll
    for (int mt = 0; mt < 4; mt++)
        offA[mt] = (uint32_t)((wm * 64 + mt * 16 + mrow) * (LROWH * 2) + kcol * 2);
#pragma unroll
    for (int p = 0; p < 4; p++)
        offB[p] = (uint32_t)(A_TILE_B + (wn * 64 + p * 16 + mrow) * (LROWH * 2) + kcol * 2);

    float acc[4][8][4];
#pragma unroll
    for (int mt = 0; mt < 4; mt++)
#pragma unroll
        for (int nt = 0; nt < 8; nt++)
#pragma unroll
            for (int r = 0; r < 4; r++) acc[mt][nt][r] = 0.f;

    const int T = K >> 5;

    auto issue = [&](int slot, int k0) {
        const uint32_t ab = sbase + (uint32_t)slot * STAGE_B;
        const uint32_t bb2 = ab + A_TILE_B;
        const __half* ag = Ab + (long long)(m0 + arow) * K + k0;
        cp16(ab + arow * (LROWH * 2) + achk * 16,        ag + achk * 8);
        cp16(ab + arow * (LROWH * 2) + (achk + 1) * 16,  ag + (achk + 1) * 8);
        const __half* bg = Bb + (long long)(n0 + brow) * K + k0;
#pragma unroll
        for (int c = 0; c < 4; c++)
            cp16(bb2 + brow * (LROWH * 2) + c * 16, bg + c * 8);
        CP_COMMIT();
    };

    issue(0, 0);
    issue(1, 32);
    issue(2, 64);

    for (int t = 0; t < T; t++) {
        CP_WAIT2();
        __syncthreads();
        if (t + 3 < T) issue((t + 3) & 3, (t + 3) * 32);
        else CP_COMMIT();   // keep wait-count invariant

        const uint32_t stg = sbase + (uint32_t)(t & 3) * STAGE_B;

#pragma unroll
        for (int kk = 0; kk < 2; kk++) {
            uint32_t a[4][4];
#pragma unroll
            for (int mt = 0; mt < 4; mt++)
                LDSM4(a[mt][0], a[mt][1], a[mt][2], a[mt][3], stg + offA[mt] + kk * 32);
            uint32_t b[8][2];
#pragma unroll
            for (int p = 0; p < 4; p++) {
                uint32_t r0, r1, r2, r3;
                LDSM4(r0, r1, r2, r3, stg + offB[p] + kk * 32);
                b[2 * p][0] = r0; b[2 * p][1] = r2;
                b[2 * p + 1][0] = r1; b[2 * p + 1][1] = r3;
            }
#pragma unroll
            for (int mt = 0; mt < 4; mt++)
#pragma unroll
                for (int nt = 0; nt < 8; nt++)
                    asm volatile(
                        "mma.sync.aligned.m16n8k16.row.col.f32.f16.f16.f32 "
                        "{%0,%1,%2,%3}, {%4,%5,%6,%7}, {%8,%9}, {%0,%1,%2,%3};"
                        : "+f"(acc[mt][nt][0]), "+f"(acc[mt][nt][1]),
                          "+f"(acc[mt][nt][2]), "+f"(acc[mt][nt][3])
                        : "r"(a[mt][0]), "r"(a[mt][1]), "r"(a[mt][2]), "r"(a[mt][3]),
                          "r"(b[nt][0]), "r"(b[nt][1]));
        }
    }

    // ---- epilogue ----
#pragma unroll
    for (int mt = 0; mt < 4; mt++) {
#pragma unroll
        for (int j = 0; j < 2; j++) {
            const int rabs = m0 + wm * 64 + mt * 16 + g + 8 * j;
#pragma unroll
            for (int nt = 0; nt < 8; nt++) {
                const int cabs = n0 + wn * 64 + nt * 8 + tg * 2;
                const float v0 = acc[mt][nt][2 * j + 0];
                const float v1 = acc[mt][nt][2 * j + 1];

                if (MODE == 0) {
                    float* C = (float*)Cv;
                    *(float2*)(C + (long long)rabs * N + cabs) =
                        make_float2(v0 + bias[cabs], v1 + bias[cabs + 1]);
                } else if (MODE == 1) {
                    __half* C = (__half*)Cv;
                    const int bb = rabs / S, s = rabs % S;
                    const int h = cabs >> 9, dk = cabs & 511;
                    *(__half2*)(C + (((long long)(bb * Hc + h) * S + s) << 9) + dk) =
                        __floats2half2_rn(v0 + bias[cabs], v1 + bias[cabs + 1]);
                } else if (MODE == 2) {
                    __half* C = (__half*)Cv;
                    const int bb = rabs / S, s = rabs % S;
                    const int h = cabs >> 9, dk = cabs & 511;
                    __half* base = C + ((long long)(bb * Hc + h) * DKc + dk) * S + s;
                    base[0]            = __float2half_rn(v0 + bias[cabs]);
                    base[(long long)S] = __float2half_rn(v1 + bias[cabs + 1]);
                } else if (MODE == 3) {
                    __half* C = (__half*)Cv;
                    *(__half2*)(C + (long long)z * sC + (long long)rabs * N + cabs) =
                        __floats2half2_rn(v0 * scale, v1 * scale);
                } else {  // MODE 4
                    __half* C = (__half*)Cv;
                    const int bb = z >> 3, h = z & 7;
                    *(__half2*)(C + (long long)(bb * SQc + rabs) * DMc + h * DKc + cabs) =
                        __floats2half2_rn(v0, v1);
                }
            }
        }
    }
}

// ---------------------------------------------------------------------------
// fp32 -> fp16 conversion (inputs / weights, once)
// ---------------------------------------------------------------------------
__global__ void cvt_h(const float4* __restrict__ in, __half2* __restrict__ out, int n4)
{
    int i = blockIdx.x * blockDim.x + threadIdx.x;
    if (i < n4) {
        float4 v = in[i];
        out[2 * i]     = __floats2half2_rn(v.x, v.y);
        out[2 * i + 1] = __floats2half2_rn(v.z, v.w);
    }
}

// ---------------------------------------------------------------------------
// Row softmax, 512 halves/row, one warp per row, fp32 internals.
// ---------------------------------------------------------------------------
__global__ void softmax512h(__half2* __restrict__ data, int nrows)
{
    const int warp = (blockIdx.x * blockDim.x + threadIdx.x) >> 5;
    const int lane = threadIdx.x & 31;
    if (warp >= nrows) return;
    __half2* row = data + (long long)warp * 256;

    float2 v[8];
    float mx = -3.4e38f;
#pragma unroll
    for (int i = 0; i < 8; i++) {
        v[i] = __half22float2(row[lane + i * 32]);
        mx = fmaxf(mx, fmaxf(v[i].x, v[i].y));
    }
#pragma unroll
    for (int o = 16; o > 0; o >>= 1) mx = fmaxf(mx, __shfl_xor_sync(0xffffffffu, mx, o));
    float sum = 0.f;
#pragma unroll
    for (int i = 0; i < 8; i++) {
        v[i].x = __expf(v[i].x - mx);
        v[i].y = __expf(v[i].y - mx);
        sum += v[i].x + v[i].y;
    }
#pragma unroll
    for (int o = 16; o > 0; o >>= 1) sum += __shfl_xor_sync(0xffffffffu, sum, o);
    const float inv = 1.0f / sum;
#pragma unroll
    for (int i = 0; i < 8; i++)
        row[lane + i * 32] = __floats2half2_rn(v[i].x * inv, v[i].y * inv);
}

// ---------------------------------------------------------------------------
// Launch
// ---------------------------------------------------------------------------
extern "C" void kernel_launch(void* const* d_in, const int* in_sizes, int n_in,
                              void* d_out, int out_size)
{
    const float* query = (const float*)d_in[0];
    const float* key   = (const float*)d_in[1];
    const float* value = (const float*)d_in[2];
    const float* imfe  = (const float*)d_in[3];
    const float* W0 = (const float*)d_in[4];  const float* b0 = (const float*)d_in[5];
    const float* W1 = (const float*)d_in[6];  const float* b1 = (const float*)d_in[7];
    const float* W2 = (const float*)d_in[8];  const float* b2 = (const float*)d_in[9];
    const float* W3 = (const float*)d_in[10]; const float* b3 = (const float*)d_in[11];
    float* out = (float*)d_out;

    __half *qh, *kh, *vh, *ih, *w0h, *w1h, *w2h, *w3h;
    __half *q, *kp, *vt, *imft, *sc, *tt, *x;
    cudaGetSymbolAddress((void**)&qh, g_qh);
    cudaGetSymbolAddress((void**)&kh, g_kh);
    cudaGetSymbolAddress((void**)&vh, g_vh);
    cudaGetSymbolAddress((void**)&ih, g_ih);
    cudaGetSymbolAddress((void**)&w0h, g_w0h);
    cudaGetSymbolAddress((void**)&w1h, g_w1h);
    cudaGetSymbolAddress((void**)&w2h, g_w2h);
    cudaGetSymbolAddress((void**)&w3h, g_w3h);
    cudaGetSymbolAddress((void**)&q,    g_q);
    cudaGetSymbolAddress((void**)&kp,   g_kp);
    cudaGetSymbolAddress((void**)&vt,   g_vt);
    cudaGetSymbolAddress((void**)&imft, g_imft);
    cudaGetSymbolAddress((void**)&sc,   g_sc);
    cudaGetSymbolAddress((void**)&tt,   g_t);
    cudaGetSymbolAddress((void**)&x,    g_x);

    cudaFuncSetAttribute(tgemm<0, 0>,   cudaFuncAttributeMaxDynamicSharedMemorySize, GEMM_SMEM);
    cudaFuncSetAttribute(tgemm<1, SQc>, cudaFuncAttributeMaxDynamicSharedMemorySize, GEMM_SMEM);
    cudaFuncSetAttribute(tgemm<1, SKc>, cudaFuncAttributeMaxDynamicSharedMemorySize, GEMM_SMEM);
    cudaFuncSetAttribute(tgemm<2, SKc>, cudaFuncAttributeMaxDynamicSharedMemorySize, GEMM_SMEM);
    cudaFuncSetAttribute(tgemm<3, 0>,   cudaFuncAttributeMaxDynamicSharedMemorySize, GEMM_SMEM);
    cudaFuncSetAttribute(tgemm<4, 0>,   cudaFuncAttributeMaxDynamicSharedMemorySize, GEMM_SMEM);

    const dim3 blk(256);
    const float scl = 1.0f / sqrtf((float)DKc);

    // ---- fp32 -> fp16 (inputs + weights) ----
    const int NQ = Bc * SQc * DMc, NK = Bc * SKc * DMc, NW = DMc * DMc;
    cvt_h<<<(NQ / 4 + 255) / 256, 256>>>((const float4*)query, (__half2*)qh, NQ / 4);
    cvt_h<<<(NK / 4 + 255) / 256, 256>>>((const float4*)key,   (__half2*)kh, NK / 4);
    cvt_h<<<(NK / 4 + 255) / 256, 256>>>((const float4*)value, (__half2*)vh, NK / 4);
    cvt_h<<<(NK / 4 + 255) / 256, 256>>>((const float4*)imfe,  (__half2*)ih, NK / 4);
    cvt_h<<<(NW / 4 + 255) / 256, 256>>>((const float4*)W0, (__half2*)w0h, NW / 4);
    cvt_h<<<(NW / 4 + 255) / 256, 256>>>((const float4*)W1, (__half2*)w1h, NW / 4);
    cvt_h<<<(NW / 4 + 255) / 256, 256>>>((const float4*)W2, (__half2*)w2h, NW / 4);
    cvt_h<<<(NW / 4 + 255) / 256, 256>>>((const float4*)W3, (__half2*)w3h, NW / 4);

    // ---- projections ----
    tgemm<1, SQc><<<dim3(DMc / BN, (Bc * SQc) / BM, 1), blk, GEMM_SMEM>>>(
        qh, w0h, b0, q, Bc * SQc, DMc, DMc, 0, 0, 0, 1.f);
    tgemm<1, SKc><<<dim3(DMc / BN, (Bc * SKc) / BM, 1), blk, GEMM_SMEM>>>(
        kh, w1h, b1, kp, Bc * SKc, DMc, DMc, 0, 0, 0, 1.f);
    tgemm<2, SKc><<<dim3(DMc / BN, (Bc * SKc) / BM, 1), blk, GEMM_SMEM>>>(
        vh, w2h, b2, vt, Bc * SKc, DMc, DMc, 0, 0, 0, 1.f);
    tgemm<2, SKc><<<dim3(DMc / BN, (Bc * SKc) / BM, 1), blk, GEMM_SMEM>>>(
        ih, w3h, b3, imft, Bc * SKc, DMc, DMc, 0, 0, 0, 1.f);

    // ---- scores = q @ k^T * scl -> softmax -> p_attn ----
    tgemm<3, 0><<<dim3(SKc / BN, SQc / BM, Bc * Hc), blk, GEMM_SMEM>>>(
        q, kp, nullptr, sc, SQc, SKc, DKc,
        (long long)SQc * DKc, (long long)SKc * DKc, (long long)SQc * SKc, scl);
    softmax512h<<<(Bc * Hc * SQc) / 8, 256>>>((__half2*)sc, Bc * Hc * SQc);

    // ---- t = p_attn @ imf -> softmax -> im_attn ----
    tgemm<3, 0><<<dim3(DKc / BN, SQc / BM, Bc * Hc), blk, GEMM_SMEM>>>(
        sc, imft, nullptr, tt, SQc, DKc, SKc,
        (long long)SQc * SKc, (long long)DKc * SKc, (long long)SQc * DKc, 1.f);
    softmax512h<<<(Bc * Hc * SQc) / 8, 256>>>((__half2*)tt, Bc * Hc * SQc);

    // ---- x = im_attn @ v (merge heads) ----
    tgemm<4, 0><<<dim3(DKc / BN, SQc / BM, Bc * Hc), blk, GEMM_SMEM>>>(
        tt, vt, nullptr, x, SQc, DKc, DKc,
        (long long)SQc * DKc, (long long)DKc * SKc, 0, 1.f);

    // ---- out = x @ W3^T + b3 (fp32 out) ----
    tgemm<0, 0><<<dim3(DMc / BN, (Bc * SQc) / BM, 1), blk, GEMM_SMEM>>>(
        x, w3h, b3, out, Bc * SQc, DMc, DMc, 0, 0, 0, 1.f);
}